// round 12
// baseline (speedup 1.0000x reference)
#include <cuda_runtime.h>
#include <cuda_fp16.h>
#include <cstdint>

#define NPTS 65536
#define MPTS 65536
#define KNB  16
#define TILE 128              // columns per CTA tile (8 pts x 16 nbrs)
#define NTILES 8192
#define GRID 296              // 2 CTAs per SM

// ---------------- device scratch ----------------
__device__ __align__(16) unsigned short g_x[(size_t)NPTS * 64];    // fp16 rows 128B
__device__ __align__(16) unsigned short g_w1e[64 * 80];            // W1|pos|bias|pad
__device__ __align__(16) unsigned short g_w2[128 * 64];
__device__ int g_idx_is64;

// ---------------- smem layout (bytes) ----------------
#define SM_W1   0                      // 64 * 176  = 11264
#define SM_W2   11264                  // 128 * 144 = 18432
#define SM_B1A  29696                  // 128 * 176 = 22528
#define SM_B1B  52224                  // 128 * 176 = 22528
#define SM_H    74752                  // 128 * 144 = 18432
#define SM_POOL 93184                  // 128 * 12 * 4 = 6144
#define SM_TOTAL 99328

// ---------------- helpers ----------------
__device__ __forceinline__ uint32_t smem_u32(const void* p) {
    uint32_t a;
    asm("{ .reg .u64 t; cvta.to.shared.u64 t, %1; cvt.u32.u64 %0, t; }" : "=r"(a) : "l"(p));
    return a;
}
__device__ __forceinline__ void ldsm4(uint32_t (&r)[4], uint32_t addr) {
    asm volatile("ldmatrix.sync.aligned.m8n8.x4.shared.b16 {%0,%1,%2,%3}, [%4];"
                 : "=r"(r[0]), "=r"(r[1]), "=r"(r[2]), "=r"(r[3]) : "r"(addr));
}
__device__ __forceinline__ void stsm4t(uint32_t addr, uint32_t r0, uint32_t r1,
                                       uint32_t r2, uint32_t r3) {
    asm volatile("stmatrix.sync.aligned.m8n8.x4.trans.shared.b16 [%0], {%1,%2,%3,%4};"
                 :: "r"(addr), "r"(r0), "r"(r1), "r"(r2), "r"(r3) : "memory");
}
__device__ __forceinline__ void mma_f32(float (&d)[4], const uint32_t (&a)[4],
                                        uint32_t b0, uint32_t b1) {
    asm volatile("mma.sync.aligned.m16n8k16.row.col.f32.f16.f16.f32 "
                 "{%0,%1,%2,%3}, {%4,%5,%6,%7}, {%8,%9}, {%0,%1,%2,%3};"
                 : "+f"(d[0]), "+f"(d[1]), "+f"(d[2]), "+f"(d[3])
                 : "r"(a[0]), "r"(a[1]), "r"(a[2]), "r"(a[3]), "r"(b0), "r"(b1));
}
#define CP16(dst, src) \
    asm volatile("cp.async.cg.shared.global [%0], [%1], 16;" :: "r"(dst), "l"(src))
#define CP_COMMIT()  asm volatile("cp.async.commit_group;" ::: "memory")
#define CP_WAIT0()   asm volatile("cp.async.wait_group 0;" ::: "memory")

__device__ __forceinline__ uint32_t packh2(float a, float b) {
    __half2 h = __floats2half2_rn(a, b);
    return *(uint32_t*)&h;
}

// ---------------- prep ----------------
__global__ __launch_bounds__(256) void prep_all_kernel(const float* __restrict__ x,
                                                       const float* __restrict__ W1,
                                                       const float* __restrict__ b1,
                                                       const float* __restrict__ W2,
                                                       const unsigned int* __restrict__ idx32)
{
    __shared__ unsigned short shhi[128 * 72];
    const int p0 = blockIdx.x * 128;
    const int tid = threadIdx.x;

    for (int idx = tid; idx < 128 * 64; idx += 256) {
        int c = idx >> 7, p = idx & 127;
        float v = x[(size_t)c * NPTS + p0 + p];
        shhi[p * 72 + c] = __half_as_ushort(__float2half_rn(v));
    }

    if (blockIdx.x == 0) {
        if (tid == 0) {
            unsigned int orv = 0;
            for (int i = 0; i < 256; i++) orv |= idx32[2 * i + 1];
            g_idx_is64 = (orv == 0u) ? 1 : 0;
        }
        for (int i = tid; i < 64 * 80; i += 256) {
            int o = i / 80, c = i % 80;
            float v = 0.0f;
            if (c < 67)       v = W1[o * 67 + c];
            else if (c == 67) v = b1[o];
            g_w1e[i] = __half_as_ushort(__float2half_rn(v));
        }
        for (int i = tid; i < 128 * 64; i += 256)
            g_w2[i] = __half_as_ushort(__float2half_rn(W2[i]));
    }
    __syncthreads();
    uint4* dh = (uint4*)(g_x + (size_t)p0 * 64);
    for (int i = tid; i < 1024; i += 256) {
        int p = i >> 3, q = i & 7;
        dh[i] = *(const uint4*)&shhi[p * 72 + q * 8];
    }
}

// ---------------- main persistent kernel: 256 thr, 2 CTAs/SM ----------------
extern __shared__ char smc[];

__global__ __launch_bounds__(256, 2)
void pointnet_mma_kernel(const float* __restrict__ pos,
                         const float* __restrict__ sup,
                         const float* __restrict__ b2,
                         const void* __restrict__ indices,
                         float* __restrict__ out)
{
    const uint32_t sb = smem_u32(smc);
    const int tid = threadIdx.x;
    const int w = tid >> 5;
    const int l = tid & 31;
    const int is64 = g_idx_is64;

    // ---- stage weights once ----
    for (int i = tid; i < 640; i += 256) {            // W1e: 64 rows x 10 chunks
        int o = i / 10, c = i % 10;
        *(uint4*)(smc + SM_W1 + o * 176 + c * 16) = *(const uint4*)(g_w1e + o * 80 + c * 8);
    }
    for (int i = tid; i < 1024; i += 256) {           // W2: 128 rows x 8 chunks
        int o = i >> 3, c = i & 7;
        *(uint4*)(smc + SM_W2 + o * 144 + c * 16) = *(const uint4*)(g_w2 + o * 64 + c * 8);
    }
    __syncthreads();

    float* poolf = (float*)(smc + SM_POOL);

    // ---- loop-invariant constants ----
    const uint32_t arow1 = sb + SM_W1 + (32 * (w & 1) + ((l >> 3) & 1) * 8 + (l & 7)) * 176;
    const uint32_t boff1 = (uint32_t)(32 * (w >> 1) + ((l >> 4) & 1) * 8 + (l & 7)) * 176;
    const uint32_t arow2 = sb + SM_W2 + (32 * (w & 3) + ((l >> 3) & 1) * 8 + (l & 7)) * 144;
    const uint32_t brow2 = sb + SM_H  + (64 * (w >> 2) + ((l >> 4) & 1) * 8 + (l & 7)) * 144;
    const uint32_t hst   = sb + SM_H + (32 * (w >> 1) + 8 * (l >> 3) + (l & 7)) * 144;

    const float bb_out = __ldg(&b2[tid >> 1]);
    const int gp   = tid >> 1;
    const int half = tid & 1;

    auto load_idx = [&](long long lin) -> int {
        if (is64) return (int)((const long long*)indices)[lin] & (NPTS - 1);
        return ((const int*)indices)[lin] & (NPTS - 1);
    };

    // ---- preload loop-invariant weight fragments into registers ----
    uint32_t wa2[4][2][4];                 // W2, full K=64
#pragma unroll
    for (int ks = 0; ks < 4; ks++) {
        uint32_t ach = (2 * ks + (l >> 4)) * 16;
        ldsm4(wa2[ks][0], arow2 + ach);
        ldsm4(wa2[ks][1], arow2 + 16 * 144 + ach);
    }
    uint32_t wa1[4][2][4];                 // W1, k-steps 0..3 (ks=4 stays in smem)
#pragma unroll
    for (int ks = 0; ks < 4; ks++) {
        uint32_t ach = (2 * ks + (l >> 4)) * 16;
        ldsm4(wa1[ks][0], arow1 + ach);
        ldsm4(wa1[ks][1], arow1 + 16 * 176 + ach);
    }

    // ---- prologue: synchronous gather of tile0 into B1A ----
    const int tile0 = blockIdx.x;
    {
        int ii = load_idx((long long)tile0 * TILE + gp);
        const char* src = (const char*)g_x + (size_t)ii * 128;
        uint32_t dst = sb + SM_B1A + gp * 176 + half * 64;
#pragma unroll
        for (int q = 0; q < 4; q++)
            CP16(dst + q * 16, src + half * 64 + q * 16);
        CP_COMMIT();
        if (tid < TILE) {
            int ii2 = load_idx((long long)tile0 * TILE + tid);
            int m = tile0 * 8 + (tid >> 4);
            float p0 = pos[0 * NPTS + ii2] - sup[0 * MPTS + m];
            float p1 = pos[1 * NPTS + ii2] - sup[1 * MPTS + m];
            float p2 = pos[2 * NPTS + ii2] - sup[2 * MPTS + m];
            uint4 c8;
            c8.x = packh2(p0, p1);
            c8.y = packh2(p2, 1.0f);
            c8.z = 0u; c8.w = 0u;
            uint4 zz = make_uint4(0u, 0u, 0u, 0u);
            *(uint4*)(smc + SM_B1A + tid * 176 + 128) = c8;
            *(uint4*)(smc + SM_B1A + tid * 176 + 144) = zz;
        }
        CP_WAIT0();
    }
    __syncthreads();

    int bufsel = 0;
    for (int tile = tile0; tile < NTILES; tile += GRID) {
        const uint32_t curB = bufsel ? SM_B1B : SM_B1A;
        const uint32_t nxtB = bufsel ? SM_B1A : SM_B1B;
        int pf = tile + GRID;
        if (pf >= NTILES) pf = tile;                  // safe redundant prefetch

        // prefetch indices for tile+GRID (latency hidden by GEMM1)
        int ii_nx = load_idx((long long)pf * TILE + gp);
        int ii_pd = 0;
        if (tid < TILE) ii_pd = load_idx((long long)pf * TILE + tid);

        // ===== GEMM1: 64 x 128, K=80 (bias+pos folded; W1 ks0-3 in regs) =====
        {
            const uint32_t brow1 = sb + curB + boff1;
            float acc[2][4][4];
#pragma unroll
            for (int i = 0; i < 2; i++)
#pragma unroll
                for (int j = 0; j < 4; j++)
#pragma unroll
                    for (int q = 0; q < 4; q++) acc[i][j][q] = 0.0f;

#pragma unroll
            for (int ks = 0; ks < 4; ks++) {
                uint32_t bch = (2 * ks + ((l >> 3) & 1)) * 16;
                uint32_t b0[4], b1r[4];
                ldsm4(b0, brow1 + bch);
                ldsm4(b1r, brow1 + 16 * 176 + bch);
                mma_f32(acc[0][0], wa1[ks][0], b0[0], b0[1]);
                mma_f32(acc[0][1], wa1[ks][0], b0[2], b0[3]);
                mma_f32(acc[0][2], wa1[ks][0], b1r[0], b1r[1]);
                mma_f32(acc[0][3], wa1[ks][0], b1r[2], b1r[3]);
                mma_f32(acc[1][0], wa1[ks][1], b0[0], b0[1]);
                mma_f32(acc[1][1], wa1[ks][1], b0[2], b0[3]);
                mma_f32(acc[1][2], wa1[ks][1], b1r[0], b1r[1]);
                mma_f32(acc[1][3], wa1[ks][1], b1r[2], b1r[3]);
            }
            {   // ks = 4 (pos/bias channels): A from smem
                uint32_t ach = (8 + (l >> 4)) * 16;
                uint32_t bch = (8 + ((l >> 3) & 1)) * 16;
                uint32_t a0[4], a1[4], b0[4], b1r[4];
                ldsm4(a0, arow1 + ach);
                ldsm4(a1, arow1 + 16 * 176 + ach);
                ldsm4(b0, brow1 + bch);
                ldsm4(b1r, brow1 + 16 * 176 + bch);
                mma_f32(acc[0][0], a0, b0[0], b0[1]);
                mma_f32(acc[0][1], a0, b0[2], b0[3]);
                mma_f32(acc[0][2], a0, b1r[0], b1r[1]);
                mma_f32(acc[0][3], a0, b1r[2], b1r[3]);
                mma_f32(acc[1][0], a1, b0[0], b0[1]);
                mma_f32(acc[1][1], a1, b0[2], b0[3]);
                mma_f32(acc[1][2], a1, b1r[0], b1r[1]);
                mma_f32(acc[1][3], a1, b1r[2], b1r[3]);
            }

            // ---- issue async gather of next tile into B1[nxt] ----
            {
                const char* src = (const char*)g_x + (size_t)ii_nx * 128;
                uint32_t dst = sb + nxtB + gp * 176 + half * 64;
#pragma unroll
                for (int q = 0; q < 4; q++)
                    CP16(dst + q * 16, src + half * 64 + q * 16);
                CP_COMMIT();
            }

            // ---- epilogue: relu -> fp16 -> H via stmatrix.trans ----
#pragma unroll
            for (int mb = 0; mb < 2; mb++) {
#pragma unroll
                for (int hf = 0; hf < 2; hf++) {
                    uint32_t r[4];
#pragma unroll
                    for (int nb = 0; nb < 4; nb++) {
                        float v0 = fmaxf(acc[mb][nb][2 * hf], 0.0f);
                        float v1 = fmaxf(acc[mb][nb][2 * hf + 1], 0.0f);
                        r[nb] = packh2(v0, v1);
                    }
                    uint32_t ch = 32 * (w & 1) + 16 * mb + 8 * hf;
                    stsm4t(hst + ch * 2, r[0], r[1], r[2], r[3]);
                }
            }
        }
        __syncthreads();

        // ===== GEMM2: 128 x 128, K=64 (W2 in regs), two N=64 passes =====
        {
            // pos/sup loads for next tile issue here; latency hidden by MMAs
            float p0 = 0.f, p1 = 0.f, p2 = 0.f;
            if (tid < TILE) {
                int m = pf * 8 + (tid >> 4);
                p0 = pos[0 * NPTS + ii_pd] - sup[0 * MPTS + m];
                p1 = pos[1 * NPTS + ii_pd] - sup[1 * MPTS + m];
                p2 = pos[2 * NPTS + ii_pd] - sup[2 * MPTS + m];
            }

#pragma unroll
            for (int nh = 0; nh < 2; nh++) {
                float acc[2][4][4];
#pragma unroll
                for (int i = 0; i < 2; i++)
#pragma unroll
                    for (int j = 0; j < 4; j++)
#pragma unroll
                        for (int q = 0; q < 4; q++) acc[i][j][q] = 0.0f;

#pragma unroll
                for (int ks = 0; ks < 4; ks++) {
                    uint32_t bch = (2 * ks + ((l >> 3) & 1)) * 16;
#pragma unroll
                    for (int nbq = 0; nbq < 2; nbq++) {
                        uint32_t b[4];
                        ldsm4(b, brow2 + (nh * 2 + nbq) * (16 * 144) + bch);
                        mma_f32(acc[0][2 * nbq],     wa2[ks][0], b[0], b[1]);
                        mma_f32(acc[0][2 * nbq + 1], wa2[ks][0], b[2], b[3]);
                        mma_f32(acc[1][2 * nbq],     wa2[ks][1], b[0], b[1]);
                        mma_f32(acc[1][2 * nbq + 1], wa2[ks][1], b[2], b[3]);
                    }
                }

                // ---- pool over K=16 cols per point (2 points this pass) ----
#pragma unroll
                for (int mb = 0; mb < 2; mb++) {
#pragma unroll
                    for (int pt = 0; pt < 2; pt++) {
                        float m0 = fmaxf(fmaxf(acc[mb][2 * pt][0], acc[mb][2 * pt][1]),
                                         fmaxf(acc[mb][2 * pt + 1][0], acc[mb][2 * pt + 1][1]));
                        float m1 = fmaxf(fmaxf(acc[mb][2 * pt][2], acc[mb][2 * pt][3]),
                                         fmaxf(acc[mb][2 * pt + 1][2], acc[mb][2 * pt + 1][3]));
                        m0 = fmaxf(m0, __shfl_xor_sync(0xffffffffu, m0, 1));
                        m0 = fmaxf(m0, __shfl_xor_sync(0xffffffffu, m0, 2));
                        m1 = fmaxf(m1, __shfl_xor_sync(0xffffffffu, m1, 1));
                        m1 = fmaxf(m1, __shfl_xor_sync(0xffffffffu, m1, 2));
                        if ((l & 3) == 0) {
                            int row = 32 * (w & 3) + 16 * mb + (l >> 2);
                            int mp  = 4 * (w >> 2) + nh * 2 + pt;
                            poolf[row * 12 + mp]       = m0;
                            poolf[(row + 8) * 12 + mp] = m1;
                        }
                    }
                }
            }

            // ---- store next tile's pos channels into B1[nxt] ----
            if (tid < TILE) {
                uint4 c8;
                c8.x = packh2(p0, p1);
                c8.y = packh2(p2, 1.0f);
                c8.z = 0u; c8.w = 0u;
                uint4 zz = make_uint4(0u, 0u, 0u, 0u);
                *(uint4*)(smc + nxtB + tid * 176 + 128) = c8;
                *(uint4*)(smc + nxtB + tid * 176 + 144) = zz;
            }
        }
        __syncthreads();

        // ---- coalesced output: [o][m], +b2 ----
        {
            int o = tid >> 1, mg = tid & 1;
            float4 v = *(const float4*)(poolf + o * 12 + mg * 4);
            v.x += bb_out; v.y += bb_out; v.z += bb_out; v.w += bb_out;
            *(float4*)(out + (size_t)o * MPTS + tile * 8 + mg * 4) = v;
        }

        CP_WAIT0();                       // B1[nxt] gather complete
        __syncthreads();                  // publish B1[nxt] (+pd) to all warps
        bufsel ^= 1;
    }
}

// ---------------------------------------------------------------------------
extern "C" void kernel_launch(void* const* d_in, const int* in_sizes, int n_in,
                              void* d_out, int out_size)
{
    const float *x = 0, *pos = 0, *sup = 0, *W1 = 0, *b1 = 0, *W2 = 0, *b2 = 0;
    const void* idx = 0;
    for (int i = 0; i < n_in; i++) {
        switch (in_sizes[i]) {
            case 4194304: x  = (const float*)d_in[i]; break;
            case 196608:  if (!pos) pos = (const float*)d_in[i];
                          else      sup = (const float*)d_in[i]; break;
            case 4288:    W1 = (const float*)d_in[i]; break;
            case 64:      b1 = (const float*)d_in[i]; break;
            case 8192:    W2 = (const float*)d_in[i]; break;
            case 128:     b2 = (const float*)d_in[i]; break;
            case 1048576: idx = d_in[i]; break;
            default: break;
        }
    }
    float* out = (float*)d_out;

    prep_all_kernel<<<NPTS / 128, 256>>>(x, W1, b1, W2, (const unsigned int*)idx);

    cudaFuncSetAttribute(pointnet_mma_kernel,
                         cudaFuncAttributeMaxDynamicSharedMemorySize, SM_TOTAL);
    pointnet_mma_kernel<<<GRID, 256, SM_TOTAL>>>(pos, sup, b2, idx, out);
}

// round 13
// speedup vs baseline: 1.0395x; 1.0395x over previous
#include <cuda_runtime.h>
#include <cuda_fp16.h>
#include <cstdint>

#define NPTS 65536
#define MPTS 65536
#define KNB  16
#define TILE 128              // columns per CTA tile (8 pts x 16 nbrs)
#define NTILES 8192
#define GRID 296              // 2 CTAs per SM

// ---------------- device scratch ----------------
__device__ __align__(16) unsigned short g_x[(size_t)NPTS * 64];    // fp16 rows 128B
__device__ __align__(16) unsigned short g_w1e[64 * 80];            // W1|pos|bias|pad
__device__ __align__(16) unsigned short g_w2[128 * 64];
__device__ int g_idx_is64;

// ---------------- smem layout (bytes) ----------------
#define SM_W1   0                      // 64 * 176  = 11264
#define SM_W2   11264                  // 128 * 144 = 18432
#define SM_B1A  29696                  // 128 * 176 = 22528
#define SM_B1B  52224                  // 128 * 176 = 22528
#define SM_H    74752                  // 128 * 144 = 18432
#define SM_POOL 93184                  // 128 * 12 * 4 = 6144
#define SM_TOTAL 99328

// ---------------- helpers ----------------
__device__ __forceinline__ uint32_t smem_u32(const void* p) {
    uint32_t a;
    asm("{ .reg .u64 t; cvta.to.shared.u64 t, %1; cvt.u32.u64 %0, t; }" : "=r"(a) : "l"(p));
    return a;
}
__device__ __forceinline__ void ldsm4(uint32_t (&r)[4], uint32_t addr) {
    asm volatile("ldmatrix.sync.aligned.m8n8.x4.shared.b16 {%0,%1,%2,%3}, [%4];"
                 : "=r"(r[0]), "=r"(r[1]), "=r"(r[2]), "=r"(r[3]) : "r"(addr));
}
__device__ __forceinline__ void stsm4t(uint32_t addr, uint32_t r0, uint32_t r1,
                                       uint32_t r2, uint32_t r3) {
    asm volatile("stmatrix.sync.aligned.m8n8.x4.trans.shared.b16 [%0], {%1,%2,%3,%4};"
                 :: "r"(addr), "r"(r0), "r"(r1), "r"(r2), "r"(r3) : "memory");
}
__device__ __forceinline__ void mma_f32(float (&d)[4], const uint32_t (&a)[4],
                                        uint32_t b0, uint32_t b1) {
    asm volatile("mma.sync.aligned.m16n8k16.row.col.f32.f16.f16.f32 "
                 "{%0,%1,%2,%3}, {%4,%5,%6,%7}, {%8,%9}, {%0,%1,%2,%3};"
                 : "+f"(d[0]), "+f"(d[1]), "+f"(d[2]), "+f"(d[3])
                 : "r"(a[0]), "r"(a[1]), "r"(a[2]), "r"(a[3]), "r"(b0), "r"(b1));
}
#define CP16(dst, src) \
    asm volatile("cp.async.cg.shared.global [%0], [%1], 16;" :: "r"(dst), "l"(src))
#define CP_COMMIT()  asm volatile("cp.async.commit_group;" ::: "memory")
#define CP_WAIT0()   asm volatile("cp.async.wait_group 0;" ::: "memory")
#define BARH(id)     asm volatile("bar.sync %0, 128;" :: "r"(id) : "memory")

__device__ __forceinline__ uint32_t packh2(float a, float b) {
    __half2 h = __floats2half2_rn(a, b);
    return *(uint32_t*)&h;
}

// ---------------- prep ----------------
__global__ __launch_bounds__(256) void prep_all_kernel(const float* __restrict__ x,
                                                       const float* __restrict__ W1,
                                                       const float* __restrict__ b1,
                                                       const float* __restrict__ W2,
                                                       const unsigned int* __restrict__ idx32)
{
    __shared__ unsigned short shhi[128 * 72];
    const int p0 = blockIdx.x * 128;
    const int tid = threadIdx.x;

    for (int idx = tid; idx < 128 * 64; idx += 256) {
        int c = idx >> 7, p = idx & 127;
        float v = x[(size_t)c * NPTS + p0 + p];
        shhi[p * 72 + c] = __half_as_ushort(__float2half_rn(v));
    }

    if (blockIdx.x == 0) {
        if (tid == 0) {
            unsigned int orv = 0;
            for (int i = 0; i < 256; i++) orv |= idx32[2 * i + 1];
            g_idx_is64 = (orv == 0u) ? 1 : 0;
        }
        for (int i = tid; i < 64 * 80; i += 256) {
            int o = i / 80, c = i % 80;
            float v = 0.0f;
            if (c < 67)       v = W1[o * 67 + c];
            else if (c == 67) v = b1[o];
            g_w1e[i] = __half_as_ushort(__float2half_rn(v));
        }
        for (int i = tid; i < 128 * 64; i += 256)
            g_w2[i] = __half_as_ushort(__float2half_rn(W2[i]));
    }
    __syncthreads();
    uint4* dh = (uint4*)(g_x + (size_t)p0 * 64);
    for (int i = tid; i < 1024; i += 256) {
        int p = i >> 3, q = i & 7;
        dh[i] = *(const uint4*)&shhi[p * 72 + q * 8];
    }
}

// ---------------- main persistent kernel: 256 thr, 2 CTAs/SM ----------------
extern __shared__ char smc[];

__global__ __launch_bounds__(256, 2)
void pointnet_mma_kernel(const float* __restrict__ pos,
                         const float* __restrict__ sup,
                         const float* __restrict__ b2,
                         const void* __restrict__ indices,
                         float* __restrict__ out)
{
    const uint32_t sb = smem_u32(smc);
    const int tid = threadIdx.x;
    const int w = tid >> 5;
    const int l = tid & 31;
    const int is64 = g_idx_is64;

    // ---- stage weights once ----
    for (int i = tid; i < 640; i += 256) {            // W1e: 64 rows x 10 chunks
        int o = i / 10, c = i % 10;
        *(uint4*)(smc + SM_W1 + o * 176 + c * 16) = *(const uint4*)(g_w1e + o * 80 + c * 8);
    }
    for (int i = tid; i < 1024; i += 256) {           // W2: 128 rows x 8 chunks
        int o = i >> 3, c = i & 7;
        *(uint4*)(smc + SM_W2 + o * 144 + c * 16) = *(const uint4*)(g_w2 + o * 64 + c * 8);
    }
    __syncthreads();

    float* poolf = (float*)(smc + SM_POOL);

    // ---- loop-invariant constants ----
    const uint32_t arow1 = sb + SM_W1 + (32 * (w & 1) + ((l >> 3) & 1) * 8 + (l & 7)) * 176;
    const uint32_t boff1 = (uint32_t)(32 * (w >> 1) + ((l >> 4) & 1) * 8 + (l & 7)) * 176;
    const uint32_t arow2 = sb + SM_W2 + (32 * (w & 3) + ((l >> 3) & 1) * 8 + (l & 7)) * 144;
    const uint32_t brow2 = sb + SM_H  + (64 * (w >> 2) + ((l >> 4) & 1) * 8 + (l & 7)) * 144;
    const uint32_t hst   = sb + SM_H + (32 * (w >> 1) + 8 * (l >> 3) + (l & 7)) * 144;
    const int hbar = 1 + (w >> 2);                    // named barrier id per H-half

    const float bb_out = __ldg(&b2[tid >> 1]);
    const int gp   = tid >> 1;
    const int half = tid & 1;

    auto load_idx = [&](long long lin) -> int {
        if (is64) return (int)((const long long*)indices)[lin] & (NPTS - 1);
        return ((const int*)indices)[lin] & (NPTS - 1);
    };

    // ---- preload W2 A-fragments into registers (loop-invariant) ----
    uint32_t wa2[4][2][4];
#pragma unroll
    for (int ks = 0; ks < 4; ks++) {
        uint32_t ach = (2 * ks + (l >> 4)) * 16;
        ldsm4(wa2[ks][0], arow2 + ach);
        ldsm4(wa2[ks][1], arow2 + 16 * 144 + ach);
    }

    // ---- prologue: synchronous gather of tile0 into B1A ----
    const int tile0 = blockIdx.x;
    {
        int ii = load_idx((long long)tile0 * TILE + gp);
        const char* src = (const char*)g_x + (size_t)ii * 128;
        uint32_t dst = sb + SM_B1A + gp * 176 + half * 64;
#pragma unroll
        for (int q = 0; q < 4; q++)
            CP16(dst + q * 16, src + half * 64 + q * 16);
        CP_COMMIT();
        if (tid < TILE) {
            int ii2 = load_idx((long long)tile0 * TILE + tid);
            int m = tile0 * 8 + (tid >> 4);
            float p0 = pos[0 * NPTS + ii2] - sup[0 * MPTS + m];
            float p1 = pos[1 * NPTS + ii2] - sup[1 * MPTS + m];
            float p2 = pos[2 * NPTS + ii2] - sup[2 * MPTS + m];
            uint4 c8;
            c8.x = packh2(p0, p1);
            c8.y = packh2(p2, 1.0f);
            c8.z = 0u; c8.w = 0u;
            uint4 zz = make_uint4(0u, 0u, 0u, 0u);
            *(uint4*)(smc + SM_B1A + tid * 176 + 128) = c8;
            *(uint4*)(smc + SM_B1A + tid * 176 + 144) = zz;
        }
        CP_WAIT0();
    }
    __syncthreads();

    int bufsel = 0;
    for (int tile = tile0; tile < NTILES; tile += GRID) {
        const uint32_t curB = bufsel ? SM_B1B : SM_B1A;
        const uint32_t nxtB = bufsel ? SM_B1A : SM_B1B;
        int pf = tile + GRID;
        if (pf >= NTILES) pf = tile;                  // safe redundant prefetch

        // prefetch indices for tile+GRID (latency hidden by GEMM1)
        int ii_nx = load_idx((long long)pf * TILE + gp);
        int ii_pd = 0;
        if (tid < TILE) ii_pd = load_idx((long long)pf * TILE + tid);

        // ===== GEMM1: 64 x 128, K=80 (bias+pos folded), B pipelined =====
        {
            const uint32_t brow1 = sb + curB + boff1;
            float acc[2][4][4];
#pragma unroll
            for (int i = 0; i < 2; i++)
#pragma unroll
                for (int j = 0; j < 4; j++)
#pragma unroll
                    for (int q = 0; q < 4; q++) acc[i][j][q] = 0.0f;

            uint32_t b0[2][4], b1r[2][4];
            {   // preload ks=0 B fragments
                uint32_t bch = ((l >> 3) & 1) * 16;
                ldsm4(b0[0], brow1 + bch);
                ldsm4(b1r[0], brow1 + 16 * 176 + bch);
            }
#pragma unroll
            for (int ks = 0; ks < 5; ks++) {
                int cur = ks & 1, nxt = cur ^ 1;
                if (ks < 4) {   // prefetch next k-step's B
                    uint32_t bch = (2 * (ks + 1) + ((l >> 3) & 1)) * 16;
                    ldsm4(b0[nxt], brow1 + bch);
                    ldsm4(b1r[nxt], brow1 + 16 * 176 + bch);
                }
                uint32_t ach = (2 * ks + (l >> 4)) * 16;
                uint32_t a0[4], a1[4];
                ldsm4(a0, arow1 + ach);
                ldsm4(a1, arow1 + 16 * 176 + ach);
                mma_f32(acc[0][0], a0, b0[cur][0], b0[cur][1]);
                mma_f32(acc[0][1], a0, b0[cur][2], b0[cur][3]);
                mma_f32(acc[0][2], a0, b1r[cur][0], b1r[cur][1]);
                mma_f32(acc[0][3], a0, b1r[cur][2], b1r[cur][3]);
                mma_f32(acc[1][0], a1, b0[cur][0], b0[cur][1]);
                mma_f32(acc[1][1], a1, b0[cur][2], b0[cur][3]);
                mma_f32(acc[1][2], a1, b1r[cur][0], b1r[cur][1]);
                mma_f32(acc[1][3], a1, b1r[cur][2], b1r[cur][3]);
            }

            // ---- issue async gather of next tile into B1[nxt] ----
            {
                const char* src = (const char*)g_x + (size_t)ii_nx * 128;
                uint32_t dst = sb + nxtB + gp * 176 + half * 64;
#pragma unroll
                for (int q = 0; q < 4; q++)
                    CP16(dst + q * 16, src + half * 64 + q * 16);
                CP_COMMIT();
            }

            // ---- epilogue: relu -> fp16 -> H via stmatrix.trans ----
#pragma unroll
            for (int mb = 0; mb < 2; mb++) {
#pragma unroll
                for (int hf = 0; hf < 2; hf++) {
                    uint32_t r[4];
#pragma unroll
                    for (int nb = 0; nb < 4; nb++) {
                        float v0 = fmaxf(acc[mb][nb][2 * hf], 0.0f);
                        float v1 = fmaxf(acc[mb][nb][2 * hf + 1], 0.0f);
                        r[nb] = packh2(v0, v1);
                    }
                    uint32_t ch = 32 * (w & 1) + 16 * mb + 8 * hf;
                    stsm4t(hst + ch * 2, r[0], r[1], r[2], r[3]);
                }
            }
        }
        // H halves are written/read by the same 4-warp groups -> named barrier
        BARH(hbar);

        // ===== GEMM2: 128 x 128, K=64 (W2 in regs), batched B loads =====
        {
            float p0 = 0.f, p1 = 0.f, p2 = 0.f;
            if (tid < TILE) {
                int m = pf * 8 + (tid >> 4);
                p0 = pos[0 * NPTS + ii_pd] - sup[0 * MPTS + m];
                p1 = pos[1 * NPTS + ii_pd] - sup[1 * MPTS + m];
                p2 = pos[2 * NPTS + ii_pd] - sup[2 * MPTS + m];
            }

            float acc[2][8][4];
#pragma unroll
            for (int i = 0; i < 2; i++)
#pragma unroll
                for (int j = 0; j < 8; j++)
#pragma unroll
                    for (int q = 0; q < 4; q++) acc[i][j][q] = 0.0f;

#pragma unroll
            for (int ks = 0; ks < 4; ks++) {
                uint32_t bch = (2 * ks + ((l >> 3) & 1)) * 16;
                uint32_t b[4][4];
#pragma unroll
                for (int nbq = 0; nbq < 4; nbq++)     // batch all loads first
                    ldsm4(b[nbq], brow2 + nbq * (16 * 144) + bch);
#pragma unroll
                for (int nbq = 0; nbq < 4; nbq++) {
                    mma_f32(acc[0][2 * nbq],     wa2[ks][0], b[nbq][0], b[nbq][1]);
                    mma_f32(acc[0][2 * nbq + 1], wa2[ks][0], b[nbq][2], b[nbq][3]);
                    mma_f32(acc[1][2 * nbq],     wa2[ks][1], b[nbq][0], b[nbq][1]);
                    mma_f32(acc[1][2 * nbq + 1], wa2[ks][1], b[nbq][2], b[nbq][3]);
                }
            }

            // ---- pool over K=16 cols per point ----
#pragma unroll
            for (int mb = 0; mb < 2; mb++) {
#pragma unroll
                for (int pt = 0; pt < 4; pt++) {
                    float m0 = fmaxf(fmaxf(acc[mb][2 * pt][0], acc[mb][2 * pt][1]),
                                     fmaxf(acc[mb][2 * pt + 1][0], acc[mb][2 * pt + 1][1]));
                    float m1 = fmaxf(fmaxf(acc[mb][2 * pt][2], acc[mb][2 * pt][3]),
                                     fmaxf(acc[mb][2 * pt + 1][2], acc[mb][2 * pt + 1][3]));
                    m0 = fmaxf(m0, __shfl_xor_sync(0xffffffffu, m0, 1));
                    m0 = fmaxf(m0, __shfl_xor_sync(0xffffffffu, m0, 2));
                    m1 = fmaxf(m1, __shfl_xor_sync(0xffffffffu, m1, 1));
                    m1 = fmaxf(m1, __shfl_xor_sync(0xffffffffu, m1, 2));
                    if ((l & 3) == 0) {
                        int row = 32 * (w & 3) + 16 * mb + (l >> 2);
                        int mp  = 4 * (w >> 2) + pt;
                        poolf[row * 12 + mp]       = m0;
                        poolf[(row + 8) * 12 + mp] = m1;
                    }
                }
            }

            // ---- store next tile's pos channels into B1[nxt] ----
            if (tid < TILE) {
                uint4 c8;
                c8.x = packh2(p0, p1);
                c8.y = packh2(p2, 1.0f);
                c8.z = 0u; c8.w = 0u;
                uint4 zz = make_uint4(0u, 0u, 0u, 0u);
                *(uint4*)(smc + nxtB + tid * 176 + 128) = c8;
                *(uint4*)(smc + nxtB + tid * 176 + 144) = zz;
            }
        }
        __syncthreads();

        // ---- coalesced output: [o][m], +b2 ----
        {
            int o = tid >> 1, mg = tid & 1;
            float4 v = *(const float4*)(poolf + o * 12 + mg * 4);
            v.x += bb_out; v.y += bb_out; v.z += bb_out; v.w += bb_out;
            *(float4*)(out + (size_t)o * MPTS + tile * 8 + mg * 4) = v;
        }

        CP_WAIT0();                       // B1[nxt] gather complete
        __syncthreads();                  // publish B1[nxt] (+pd) to all warps
        bufsel ^= 1;
    }
}

// ---------------------------------------------------------------------------
extern "C" void kernel_launch(void* const* d_in, const int* in_sizes, int n_in,
                              void* d_out, int out_size)
{
    const float *x = 0, *pos = 0, *sup = 0, *W1 = 0, *b1 = 0, *W2 = 0, *b2 = 0;
    const void* idx = 0;
    for (int i = 0; i < n_in; i++) {
        switch (in_sizes[i]) {
            case 4194304: x  = (const float*)d_in[i]; break;
            case 196608:  if (!pos) pos = (const float*)d_in[i];
                          else      sup = (const float*)d_in[i]; break;
            case 4288:    W1 = (const float*)d_in[i]; break;
            case 64:      b1 = (const float*)d_in[i]; break;
            case 8192:    W2 = (const float*)d_in[i]; break;
            case 128:     b2 = (const float*)d_in[i]; break;
            case 1048576: idx = d_in[i]; break;
            default: break;
        }
    }
    float* out = (float*)d_out;

    prep_all_kernel<<<NPTS / 128, 256>>>(x, W1, b1, W2, (const unsigned int*)idx);

    cudaFuncSetAttribute(pointnet_mma_kernel,
                         cudaFuncAttributeMaxDynamicSharedMemorySize, SM_TOTAL);
    pointnet_mma_kernel<<<GRID, 256, SM_TOTAL>>>(pos, sup, b2, idx, out);
}